// round 1
// baseline (speedup 1.0000x reference)
#include <cuda_runtime.h>
#include <math.h>

#define SIZE 1000

// ---------------------------------------------------------------------------
// Kernel 1: zero the [1000,1000,10] fp32 output (40 MB) with float4 stores.
// This is the HBM roofline term: ~40MB write-only.
// ---------------------------------------------------------------------------
__global__ void vi_zero_kernel(float4* __restrict__ out, int n4) {
    int i = blockIdx.x * blockDim.x + threadIdx.x;
    if (i < n4) out[i] = make_float4(0.f, 0.f, 0.f, 0.f);
}

// ---------------------------------------------------------------------------
// Exact per-element mask value (pre-transpose coords i=row, j=col), mirroring
// the reference tanh chain bit-for-bit in fp32:
//   x1 = tanh(1e5*(a-j)),  y1 = tanh(1e5*(b-(i+1)))
//   x3 = tanh(1e5*(a-(j+1))), y3 = tanh(1e5*(b-i))
//   mask = tanh(1e5*y1*x1) * tanh(1e5*y3*x3);  return (1-mask)/2
// ---------------------------------------------------------------------------
__device__ __forceinline__ float vi_maskval(float a, float b, int i, int j) {
    float x1 = tanhf(100000.0f * (a - (float)j));
    float y1 = tanhf(100000.0f * (b - (float)(i + 1)));
    float x3 = tanhf(100000.0f * (a - (float)(j + 1)));
    float y3 = tanhf(100000.0f * (b - (float)i));
    float m1 = tanhf(100000.0f * (y1 * x1));
    float m3 = tanhf(100000.0f * (y3 * x3));
    return (1.0f - m1 * m3) * 0.5f;
}

// Transposed mask with zero padding: mask_t(p,q) = mask(i=q, j=p)
__device__ __forceinline__ float vi_mt(float a, float b, int p, int q) {
    if (p < 0 || p >= SIZE || q < 0 || q >= SIZE) return 0.0f;
    return vi_maskval(a, b, q, p);
}

// ---------------------------------------------------------------------------
// Kernel 2: for each of the 8 input points, evaluate relu(plus_conv - 3) on a
// 7x7 window around (floor(a), floor(b)) — analysis shows all nonzeros of the
// full 1000x1000 result live within +/-2 cells of that point. Scatter-max into
// out[p,q,cls]. atomicMax on int bits is exact for non-negative floats.
// ---------------------------------------------------------------------------
__global__ void vi_point_kernel(const float* __restrict__ z_pos,
                                const int* __restrict__ z_cls,
                                float* __restrict__ out) {
    int n = blockIdx.x;      // 8 blocks, one per input point
    int t = threadIdx.x;     // 49 threads = 7x7 window
    float a = z_pos[2 * n + 0] * 1000.0f;
    float b = z_pos[2 * n + 1] * 1000.0f;
    int jc = (int)floorf(a);
    int ic = (int)floorf(b);

    int p = jc + (t % 7) - 3;
    int q = ic + (t / 7) - 3;
    if (p < 0 || p >= SIZE || q < 0 || q >= SIZE) return;

    // plus-shaped 3x3 conv, SAME padding (zeros), on transposed mask
    float conv = vi_mt(a, b, p - 1, q) + vi_mt(a, b, p + 1, q) +
                 vi_mt(a, b, p, q - 1) + vi_mt(a, b, p, q + 1);
    float v = conv - 3.0f;   // relu
    if (v <= 0.0f) return;

    int c = z_cls[n];        // one-hot class channel
    atomicMax((int*)&out[((long long)p * SIZE + q) * 10 + c], __float_as_int(v));
}

extern "C" void kernel_launch(void* const* d_in, const int* in_sizes, int n_in,
                              void* d_out, int out_size) {
    const float* z_pos = (const float*)d_in[0];  // [8,2] fp32
    const int* z_cls = (const int*)d_in[1];      // [8] int32
    float* out = (float*)d_out;                  // [1000,1000,10] fp32

    int n4 = out_size / 4;                       // 10,000,000 / 4 = 2,500,000
    vi_zero_kernel<<<(n4 + 255) / 256, 256>>>((float4*)out, n4);
    vi_point_kernel<<<8, 49>>>(z_pos, z_cls, out);
}